// round 1
// baseline (speedup 1.0000x reference)
#include <cuda_runtime.h>
#include <math.h>

#define NN 50000
#define NE 1000000
#define NQ 100000
#define FD 256

// Scratch (allocation-free rule: __device__ globals). 2 x 51.2 MB.
__device__ __align__(128) float g_bufA[(size_t)NN * FD]; // h tmp (x@W1, then h1r@W2)
__device__ __align__(128) float g_bufB[(size_t)NN * FD]; // agg1, then agg2

// ---------------------------------------------------------------------------
// SGEMM: C[M,N] = op(A)[M,K] @ B[K,N], all row-major.
// op(A) = A                          if !RELU_BIAS
// op(A)[m][k] = relu(A[m][k]+bias[k]) if RELU_BIAS   (fuses relu(agg1+b1))
// 128x128 block tile, BK=8, 256 threads, 8x8 per-thread microtile.
// ---------------------------------------------------------------------------
template <bool RELU_BIAS>
__global__ __launch_bounds__(256) void sgemm128(
    const float* __restrict__ A, const float* __restrict__ B,
    const float* __restrict__ bias, float* __restrict__ C,
    int M, int N, int K)
{
    __shared__ float As[8][128];
    __shared__ float Bs[8][128];

    const int tid = threadIdx.x;
    const int rowBase = blockIdx.y * 128;
    const int colBase = blockIdx.x * 128;

    const int aRow = tid >> 1;          // 0..127
    const int aCol = (tid & 1) * 4;     // 0 or 4
    const int bRow = tid >> 5;          // 0..7
    const int bCol = (tid & 31) * 4;    // 0..124

    const int tx = tid & 15;            // 0..15 -> 8 output cols
    const int ty = tid >> 4;            // 0..15 -> 8 output rows

    float acc[8][8];
#pragma unroll
    for (int i = 0; i < 8; i++)
#pragma unroll
        for (int j = 0; j < 8; j++) acc[i][j] = 0.f;

    for (int kt = 0; kt < K; kt += 8) {
        // Load A tile (transpose into As[k][m])
        float4 av;
        const int gr = rowBase + aRow;
        if (gr < M)
            av = *(const float4*)(A + (size_t)gr * K + kt + aCol);
        else
            av = make_float4(0.f, 0.f, 0.f, 0.f);
        if (RELU_BIAS) {
            av.x = fmaxf(av.x + bias[kt + aCol + 0], 0.f);
            av.y = fmaxf(av.y + bias[kt + aCol + 1], 0.f);
            av.z = fmaxf(av.z + bias[kt + aCol + 2], 0.f);
            av.w = fmaxf(av.w + bias[kt + aCol + 3], 0.f);
        }
        As[aCol + 0][aRow] = av.x;
        As[aCol + 1][aRow] = av.y;
        As[aCol + 2][aRow] = av.z;
        As[aCol + 3][aRow] = av.w;

        // Load B tile
        *(float4*)&Bs[bRow][bCol] =
            *(const float4*)(B + (size_t)(kt + bRow) * N + colBase + bCol);

        __syncthreads();

#pragma unroll
        for (int kk = 0; kk < 8; ++kk) {
            float a[8], b[8];
            *(float4*)&a[0] = *(float4*)&As[kk][ty * 8];
            *(float4*)&a[4] = *(float4*)&As[kk][ty * 8 + 4];
            *(float4*)&b[0] = *(float4*)&Bs[kk][tx * 8];
            *(float4*)&b[4] = *(float4*)&Bs[kk][tx * 8 + 4];
#pragma unroll
            for (int i = 0; i < 8; i++)
#pragma unroll
                for (int j = 0; j < 8; j++)
                    acc[i][j] = fmaf(a[i], b[j], acc[i][j]);
        }
        __syncthreads();
    }

#pragma unroll
    for (int i = 0; i < 8; i++) {
        const int row = rowBase + ty * 8 + i;
        if (row < M) {
            float4 v0 = make_float4(acc[i][0], acc[i][1], acc[i][2], acc[i][3]);
            float4 v1 = make_float4(acc[i][4], acc[i][5], acc[i][6], acc[i][7]);
            float* cp = C + (size_t)row * N + colBase + tx * 8;
            *(float4*)cp = v0;
            *(float4*)(cp + 4) = v1;
        }
    }
}

// ---------------------------------------------------------------------------
// Edge scatter: agg[dst] += w_e * h[src].  64 threads per edge, one float4
// per thread, vector reduction (red.global.add.v4.f32).
// ---------------------------------------------------------------------------
__global__ __launch_bounds__(256) void scatter_edges(
    const float* __restrict__ h, const int* __restrict__ ei,
    const float* __restrict__ w, float* __restrict__ agg)
{
    const int e = blockIdx.x * 4 + (threadIdx.x >> 6);
    if (e >= NE) return;
    const int j = (threadIdx.x & 63) * 4;

    const int src = ei[e];
    const int dst = ei[NE + e];
    const float wt = w[e];

    float4 v = *(const float4*)(h + (size_t)src * FD + j);
    v.x *= wt; v.y *= wt; v.z *= wt; v.w *= wt;

    float* p = agg + (size_t)dst * FD + j;
    asm volatile("red.global.add.v4.f32 [%0], {%1,%2,%3,%4};"
                 :: "l"(p), "f"(v.x), "f"(v.y), "f"(v.z), "f"(v.w)
                 : "memory");
}

// ---------------------------------------------------------------------------
// Query scorer: for each query (n0, n1):
//   q = concat(h2[n0], h2[n1]) with h2 = agg2 + b2
//   logits = q @ Wl + bl ;  out = log_softmax(logits)
// One warp per query.
// ---------------------------------------------------------------------------
__global__ __launch_bounds__(256) void query_kernel(
    const float* __restrict__ agg2, const float* __restrict__ b2,
    const int* __restrict__ q, const float* __restrict__ Wl,
    const float* __restrict__ bl, float* __restrict__ out)
{
    __shared__ float sWl[512 * 2];
    __shared__ float sb2[FD];

    const int tid = threadIdx.x;
    for (int i = tid; i < 1024; i += 256) sWl[i] = Wl[i];
    if (tid < FD) sb2[tid] = b2[tid];
    __syncthreads();

    const int warp = tid >> 5;
    const int lane = tid & 31;
    const int qi = blockIdx.x * 8 + warp;
    if (qi >= NQ) return;

    const int n0 = q[qi * 2 + 0];
    const int n1 = q[qi * 2 + 1];

    float l0 = 0.f, l1 = 0.f;
#pragma unroll
    for (int t = 0; t < 8; t++) {
        const int jj = t * 32 + lane;
        const float v = agg2[(size_t)n0 * FD + jj] + sb2[jj];
        l0 = fmaf(v, sWl[jj * 2 + 0], l0);
        l1 = fmaf(v, sWl[jj * 2 + 1], l1);
    }
#pragma unroll
    for (int t = 0; t < 8; t++) {
        const int jj = t * 32 + lane;
        const float v = agg2[(size_t)n1 * FD + jj] + sb2[jj];
        l0 = fmaf(v, sWl[(256 + jj) * 2 + 0], l0);
        l1 = fmaf(v, sWl[(256 + jj) * 2 + 1], l1);
    }
#pragma unroll
    for (int o = 16; o; o >>= 1) {
        l0 += __shfl_down_sync(0xFFFFFFFFu, l0, o);
        l1 += __shfl_down_sync(0xFFFFFFFFu, l1, o);
    }
    if (lane == 0) {
        l0 += bl[0];
        l1 += bl[1];
        const float m = fmaxf(l0, l1);
        const float lse = m + logf(expf(l0 - m) + expf(l1 - m));
        out[qi * 2 + 0] = l0 - lse;
        out[qi * 2 + 1] = l1 - lse;
    }
}

extern "C" void kernel_launch(void* const* d_in, const int* in_sizes, int n_in,
                              void* d_out, int out_size)
{
    const float* x  = (const float*)d_in[0];
    const int*   ei = (const int*)  d_in[1];
    const int*   q  = (const int*)  d_in[2];
    const float* w  = (const float*)d_in[3];
    const float* W1 = (const float*)d_in[4];
    const float* b1 = (const float*)d_in[5];
    const float* W2 = (const float*)d_in[6];
    const float* b2 = (const float*)d_in[7];
    const float* Wl = (const float*)d_in[8];
    const float* bl = (const float*)d_in[9];
    float* out = (float*)d_out;

    float *bufA, *bufB;
    cudaGetSymbolAddress((void**)&bufA, g_bufA);
    cudaGetSymbolAddress((void**)&bufB, g_bufB);
    const size_t bufBytes = (size_t)NN * FD * sizeof(float);

    const dim3 gemmGrid(FD / 128, (NN + 127) / 128);   // (2, 391)
    const int scatterBlocks = NE / 4;                  // 250000

    // 1) zero agg1
    cudaMemsetAsync(bufB, 0, bufBytes, 0);
    // 2) h1tmp = x @ W1
    sgemm128<false><<<gemmGrid, 256>>>(x, W1, nullptr, bufA, NN, FD, FD);
    // 3) agg1[dst] += w * h1tmp[src]
    scatter_edges<<<scatterBlocks, 256>>>(bufA, ei, w, bufB);
    // 4) h2tmp = relu(agg1 + b1) @ W2
    sgemm128<true><<<gemmGrid, 256>>>(bufB, W2, b1, bufA, NN, FD, FD);
    // 5) zero agg2
    cudaMemsetAsync(bufB, 0, bufBytes, 0);
    // 6) agg2[dst] += w * h2tmp[src]
    scatter_edges<<<scatterBlocks, 256>>>(bufA, ei, w, bufB);
    // 7) query scoring + log_softmax
    query_kernel<<<(NQ + 7) / 8, 256>>>(bufB, b2, q, Wl, bl, out);
}

// round 5
// speedup vs baseline: 1.4974x; 1.4974x over previous
#include <cuda_runtime.h>
#include <math.h>

#define NN 50000
#define NE 1000000
#define NQ 100000
#define FD 256

// Scratch (allocation-free rule: __device__ globals).
__device__ __align__(128) float g_bufA[(size_t)NN * FD]; // h tmp (x@W1, then h1r@W2)
__device__ __align__(128) float g_bufB[(size_t)NN * FD]; // agg1, then agg2
__device__ int   g_deg[NN];
__device__ int   g_off[NN + 1];
__device__ int   g_pos[NN];
__device__ int   g_srcS[NE];   // src sorted by dst
__device__ float g_wS[NE];     // weight sorted by dst

// ---------------------------------------------------------------------------
// Edge preprocessing: counting sort by destination node.
// ---------------------------------------------------------------------------
__global__ __launch_bounds__(256) void hist_kernel(const int* __restrict__ ei)
{
    const int e = blockIdx.x * 256 + threadIdx.x;
    if (e < NE) atomicAdd(&g_deg[ei[NE + e]], 1);
}

// Single-block exclusive scan over g_deg -> g_off (NN elements + total).
__global__ __launch_bounds__(1024) void scan_kernel()
{
    __shared__ int warpSums[32];
    const int lane = threadIdx.x & 31;
    const int wid  = threadIdx.x >> 5;
    int carry = 0;

    for (int base = 0; base < NN; base += 1024) {
        const int i = base + threadIdx.x;
        const int v = (i < NN) ? g_deg[i] : 0;
        int x = v;
#pragma unroll
        for (int o = 1; o < 32; o <<= 1) {
            int y = __shfl_up_sync(0xFFFFFFFFu, x, o);
            if (lane >= o) x += y;
        }
        if (lane == 31) warpSums[wid] = x;
        __syncthreads();
        if (threadIdx.x < 32) {
            int s = warpSums[threadIdx.x];
#pragma unroll
            for (int o = 1; o < 32; o <<= 1) {
                int y = __shfl_up_sync(0xFFFFFFFFu, s, o);
                if (threadIdx.x >= o) s += y;
            }
            warpSums[threadIdx.x] = s;
        }
        __syncthreads();
        const int warpPre = (wid > 0) ? warpSums[wid - 1] : 0;
        if (i < NN) g_off[i] = carry + warpPre + x - v;
        const int blockTotal = warpSums[31];
        __syncthreads();
        carry += blockTotal;
    }
    if (threadIdx.x == 0) g_off[NN] = carry;
}

__global__ __launch_bounds__(256) void sort_kernel(
    const int* __restrict__ ei, const float* __restrict__ w)
{
    const int e = blockIdx.x * 256 + threadIdx.x;
    if (e >= NE) return;
    const int dst = ei[NE + e];
    const int p = g_off[dst] + atomicAdd(&g_pos[dst], 1);
    g_srcS[p] = ei[e];
    g_wS[p]   = w[e];
}

// ---------------------------------------------------------------------------
// Segment aggregation: out[n] = sum_{e in seg(n)} w_e * h[src_e].
// 64 threads per node (one float4 lane each), register accumulation,
// single streamed store. 4-edge unroll for MLP=4 row loads.
// ---------------------------------------------------------------------------
__global__ __launch_bounds__(256) void aggregate_kernel(
    const float* __restrict__ h, float* __restrict__ out)
{
    const int node = blockIdx.x * 4 + (threadIdx.x >> 6);
    if (node >= NN) return;
    const int j = (threadIdx.x & 63) * 4;

    const int eBeg = g_off[node];
    const int eEnd = g_off[node + 1];

    float4 acc = make_float4(0.f, 0.f, 0.f, 0.f);
    int e = eBeg;
    for (; e + 3 < eEnd; e += 4) {
        const int   s0 = g_srcS[e],     s1 = g_srcS[e + 1];
        const int   s2 = g_srcS[e + 2], s3 = g_srcS[e + 3];
        const float w0 = g_wS[e],       w1 = g_wS[e + 1];
        const float w2 = g_wS[e + 2],   w3 = g_wS[e + 3];
        const float4 v0 = *(const float4*)(h + (size_t)s0 * FD + j);
        const float4 v1 = *(const float4*)(h + (size_t)s1 * FD + j);
        const float4 v2 = *(const float4*)(h + (size_t)s2 * FD + j);
        const float4 v3 = *(const float4*)(h + (size_t)s3 * FD + j);
        acc.x = fmaf(w0, v0.x, acc.x); acc.y = fmaf(w0, v0.y, acc.y);
        acc.z = fmaf(w0, v0.z, acc.z); acc.w = fmaf(w0, v0.w, acc.w);
        acc.x = fmaf(w1, v1.x, acc.x); acc.y = fmaf(w1, v1.y, acc.y);
        acc.z = fmaf(w1, v1.z, acc.z); acc.w = fmaf(w1, v1.w, acc.w);
        acc.x = fmaf(w2, v2.x, acc.x); acc.y = fmaf(w2, v2.y, acc.y);
        acc.z = fmaf(w2, v2.z, acc.z); acc.w = fmaf(w2, v2.w, acc.w);
        acc.x = fmaf(w3, v3.x, acc.x); acc.y = fmaf(w3, v3.y, acc.y);
        acc.z = fmaf(w3, v3.z, acc.z); acc.w = fmaf(w3, v3.w, acc.w);
    }
    for (; e < eEnd; e++) {
        const int   s0 = g_srcS[e];
        const float w0 = g_wS[e];
        const float4 v0 = *(const float4*)(h + (size_t)s0 * FD + j);
        acc.x = fmaf(w0, v0.x, acc.x); acc.y = fmaf(w0, v0.y, acc.y);
        acc.z = fmaf(w0, v0.z, acc.z); acc.w = fmaf(w0, v0.w, acc.w);
    }
    *(float4*)(out + (size_t)node * FD + j) = acc;
}

// ---------------------------------------------------------------------------
// SGEMM: C[M,N] = op(A)[M,K] @ B[K,N], row-major.
// op fuses relu(A + bias) when RELU_BIAS.
// Register-prefetch software pipeline over the K tiles.
// ---------------------------------------------------------------------------
template <bool RELU_BIAS>
__global__ __launch_bounds__(256) void sgemm128(
    const float* __restrict__ A, const float* __restrict__ B,
    const float* __restrict__ bias, float* __restrict__ C,
    int M, int N, int K)
{
    __shared__ float As[8][128];
    __shared__ float Bs[8][128];

    const int tid = threadIdx.x;
    const int rowBase = blockIdx.y * 128;
    const int colBase = blockIdx.x * 128;

    const int aRow = tid >> 1;
    const int aCol = (tid & 1) * 4;
    const int bRow = tid >> 5;
    const int bCol = (tid & 31) * 4;

    const int tx = tid & 15;
    const int ty = tid >> 4;

    const int gr = rowBase + aRow;
    const bool rowOK = (gr < M);
    const float* Aptr = A + (size_t)(rowOK ? gr : 0) * K + aCol;
    const float* Bptr = B + (size_t)bRow * N + colBase + bCol;

    float acc[8][8];
#pragma unroll
    for (int i = 0; i < 8; i++)
#pragma unroll
        for (int j = 0; j < 8; j++) acc[i][j] = 0.f;

    // Prologue: fetch tile 0 into registers.
    float4 av = rowOK ? *(const float4*)(Aptr) : make_float4(0.f, 0.f, 0.f, 0.f);
    float4 bv = *(const float4*)(Bptr);

    for (int kt = 0; kt < K; kt += 8) {
        // Commit current tile to SMEM (with fused bias+relu on A).
        float4 a = av;
        if (RELU_BIAS) {
            a.x = fmaxf(a.x + bias[kt + aCol + 0], 0.f);
            a.y = fmaxf(a.y + bias[kt + aCol + 1], 0.f);
            a.z = fmaxf(a.z + bias[kt + aCol + 2], 0.f);
            a.w = fmaxf(a.w + bias[kt + aCol + 3], 0.f);
        }
        As[aCol + 0][aRow] = a.x;
        As[aCol + 1][aRow] = a.y;
        As[aCol + 2][aRow] = a.z;
        As[aCol + 3][aRow] = a.w;
        *(float4*)&Bs[bRow][bCol] = bv;

        __syncthreads();

        // Prefetch next tile while computing this one.
        if (kt + 8 < K) {
            av = rowOK ? *(const float4*)(Aptr + kt + 8)
                       : make_float4(0.f, 0.f, 0.f, 0.f);
            bv = *(const float4*)(Bptr + (size_t)(kt + 8) * N);
        }

#pragma unroll
        for (int kk = 0; kk < 8; ++kk) {
            float ar[8], br[8];
            *(float4*)&ar[0] = *(float4*)&As[kk][ty * 8];
            *(float4*)&ar[4] = *(float4*)&As[kk][ty * 8 + 4];
            *(float4*)&br[0] = *(float4*)&Bs[kk][tx * 8];
            *(float4*)&br[4] = *(float4*)&Bs[kk][tx * 8 + 4];
#pragma unroll
            for (int i = 0; i < 8; i++)
#pragma unroll
                for (int j = 0; j < 8; j++)
                    acc[i][j] = fmaf(ar[i], br[j], acc[i][j]);
        }
        __syncthreads();
    }

#pragma unroll
    for (int i = 0; i < 8; i++) {
        const int row = rowBase + ty * 8 + i;
        if (row < M) {
            float4 v0 = make_float4(acc[i][0], acc[i][1], acc[i][2], acc[i][3]);
            float4 v1 = make_float4(acc[i][4], acc[i][5], acc[i][6], acc[i][7]);
            float* cp = C + (size_t)row * N + colBase + tx * 8;
            *(float4*)cp = v0;
            *(float4*)(cp + 4) = v1;
        }
    }
}

// ---------------------------------------------------------------------------
// Query scorer (one warp per query) + log_softmax over 2 classes.
// ---------------------------------------------------------------------------
__global__ __launch_bounds__(256) void query_kernel(
    const float* __restrict__ agg2, const float* __restrict__ b2,
    const int* __restrict__ q, const float* __restrict__ Wl,
    const float* __restrict__ bl, float* __restrict__ out)
{
    __shared__ float sWl[512 * 2];
    __shared__ float sb2[FD];

    const int tid = threadIdx.x;
    for (int i = tid; i < 1024; i += 256) sWl[i] = Wl[i];
    if (tid < FD) sb2[tid] = b2[tid];
    __syncthreads();

    const int warp = tid >> 5;
    const int lane = tid & 31;
    const int qi = blockIdx.x * 8 + warp;
    if (qi >= NQ) return;

    const int n0 = q[qi * 2 + 0];
    const int n1 = q[qi * 2 + 1];

    float l0 = 0.f, l1 = 0.f;
#pragma unroll
    for (int t = 0; t < 8; t++) {
        const int jj = t * 32 + lane;
        const float v = agg2[(size_t)n0 * FD + jj] + sb2[jj];
        l0 = fmaf(v, sWl[jj * 2 + 0], l0);
        l1 = fmaf(v, sWl[jj * 2 + 1], l1);
    }
#pragma unroll
    for (int t = 0; t < 8; t++) {
        const int jj = t * 32 + lane;
        const float v = agg2[(size_t)n1 * FD + jj] + sb2[jj];
        l0 = fmaf(v, sWl[(256 + jj) * 2 + 0], l0);
        l1 = fmaf(v, sWl[(256 + jj) * 2 + 1], l1);
    }
#pragma unroll
    for (int o = 16; o; o >>= 1) {
        l0 += __shfl_down_sync(0xFFFFFFFFu, l0, o);
        l1 += __shfl_down_sync(0xFFFFFFFFu, l1, o);
    }
    if (lane == 0) {
        l0 += bl[0];
        l1 += bl[1];
        const float m = fmaxf(l0, l1);
        const float lse = m + logf(expf(l0 - m) + expf(l1 - m));
        out[qi * 2 + 0] = l0 - lse;
        out[qi * 2 + 1] = l1 - lse;
    }
}

extern "C" void kernel_launch(void* const* d_in, const int* in_sizes, int n_in,
                              void* d_out, int out_size)
{
    const float* x  = (const float*)d_in[0];
    const int*   ei = (const int*)  d_in[1];
    const int*   q  = (const int*)  d_in[2];
    const float* w  = (const float*)d_in[3];
    const float* W1 = (const float*)d_in[4];
    const float* b1 = (const float*)d_in[5];
    const float* W2 = (const float*)d_in[6];
    const float* b2 = (const float*)d_in[7];
    const float* Wl = (const float*)d_in[8];
    const float* bl = (const float*)d_in[9];
    float* out = (float*)d_out;

    float *bufA, *bufB;
    int *degP, *posP;
    cudaGetSymbolAddress((void**)&bufA, g_bufA);
    cudaGetSymbolAddress((void**)&bufB, g_bufB);
    cudaGetSymbolAddress((void**)&degP, g_deg);
    cudaGetSymbolAddress((void**)&posP, g_pos);

    const dim3 gemmGrid(FD / 128, (NN + 127) / 128);   // (2, 391)
    const int edgeBlocks = (NE + 255) / 256;
    const int aggBlocks  = (NN + 3) / 4;

    // ---- edge preprocessing: counting sort by dst (shared by both convs) ----
    cudaMemsetAsync(degP, 0, NN * sizeof(int), 0);
    cudaMemsetAsync(posP, 0, NN * sizeof(int), 0);
    hist_kernel<<<edgeBlocks, 256>>>(ei);
    scan_kernel<<<1, 1024>>>();
    sort_kernel<<<edgeBlocks, 256>>>(ei, w);

    // ---- layer 1 ----
    sgemm128<false><<<gemmGrid, 256>>>(x, W1, nullptr, bufA, NN, FD, FD);
    aggregate_kernel<<<aggBlocks, 256>>>(bufA, bufB);

    // ---- layer 2 (relu + b1 fused into GEMM A-operand) ----
    sgemm128<true><<<gemmGrid, 256>>>(bufB, W2, b1, bufA, NN, FD, FD);
    aggregate_kernel<<<aggBlocks, 256>>>(bufA, bufB);

    // ---- query scoring + log_softmax (b2 fused) ----
    query_kernel<<<(NQ + 7) / 8, 256>>>(bufB, b2, q, Wl, bl, out);
}

// round 13
// speedup vs baseline: 1.6802x; 1.1221x over previous
#include <cuda_runtime.h>
#include <math.h>
#include <stdint.h>

#define NN 50000
#define NE 1000000
#define NQ 100000
#define FD 256

// ---------------------------------------------------------------------------
// Scratch (allocation-free rule: __device__ globals).
// ---------------------------------------------------------------------------
__device__ __align__(128) float g_bufA[(size_t)NN * FD]; // h tmp
__device__ __align__(128) float g_bufB[(size_t)NN * FD]; // agg1, then agg2
__device__ int   g_deg[NN];
__device__ int   g_off[NN + 1];
__device__ int   g_pos[NN];
__device__ int   g_srcS[NE];
__device__ float g_wS[NE];
// Pre-split transposed weights: BT[n][k] = W[k][n], tf32 hi/lo parts.
__device__ __align__(128) float g_B1hi[FD * FD];
__device__ __align__(128) float g_B1lo[FD * FD];
__device__ __align__(128) float g_B2hi[FD * FD];
__device__ __align__(128) float g_B2lo[FD * FD];

__device__ __forceinline__ float tf32_rna(float x) {
    uint32_t u;
    asm("cvt.rna.tf32.f32 %0, %1;" : "=r"(u) : "f"(x));
    return __uint_as_float(u);
}

// m16n8k8 tf32 mma (HMMA path, baseline PTX — no tcgen05 needed).
#define MMA_TF32(d, a, b) \
    asm volatile("mma.sync.aligned.m16n8k8.row.col.f32.tf32.tf32.f32 " \
        "{%0,%1,%2,%3}, {%4,%5,%6,%7}, {%8,%9}, {%0,%1,%2,%3};" \
        : "+f"((d)[0]), "+f"((d)[1]), "+f"((d)[2]), "+f"((d)[3]) \
        : "r"((a)[0]), "r"((a)[1]), "r"((a)[2]), "r"((a)[3]), \
          "r"((b)[0]), "r"((b)[1]))

// ---------------------------------------------------------------------------
// Weight transpose + tf32 hi/lo split (runs once per launch, trivial cost).
// ---------------------------------------------------------------------------
__global__ __launch_bounds__(256) void wsplit_kernel(
    const float* __restrict__ W1, const float* __restrict__ W2)
{
    const int n = blockIdx.x;
    const int k = threadIdx.x;
    {
        const float v = W1[k * FD + n];
        const float h = tf32_rna(v);
        g_B1hi[n * FD + k] = h;
        g_B1lo[n * FD + k] = tf32_rna(v - h);
    }
    {
        const float v = W2[k * FD + n];
        const float h = tf32_rna(v);
        g_B2hi[n * FD + k] = h;
        g_B2lo[n * FD + k] = tf32_rna(v - h);
    }
}

// ---------------------------------------------------------------------------
// 3xTF32 mma.sync GEMM: C[M,256] = op(A)[M,256] @ W.
// op = relu(A + bias) when RELU_BIAS. W passed as transposed hi/lo (BT[n][k]).
// CTA tile 128x128, 8 warps of 64x32, K chunks of 64, single SMEM buffer.
// SMEM rows padded to 68 floats -> fragment LDS.32 hit all 32 banks.
// ---------------------------------------------------------------------------
#define KC 64
#define LDP 68
#define A_FLOATS (128 * LDP)
#define GEMM_SMEM_BYTES (4 * A_FLOATS * 4)

template <bool RELU_BIAS>
__global__ __launch_bounds__(256, 1) void gemm_mma(
    const float* __restrict__ A,
    const float* __restrict__ BThi, const float* __restrict__ BTlo,
    const float* __restrict__ bias, float* __restrict__ C)
{
    extern __shared__ float sm[];
    float* AH = sm;
    float* AL = sm + A_FLOATS;
    float* BH = sm + 2 * A_FLOATS;
    float* BL = sm + 3 * A_FLOATS;

    const int tid = threadIdx.x;
    const int wid = tid >> 5;
    const int lane = tid & 31;
    const int g = lane >> 2;    // group id (row within fragment)
    const int t = lane & 3;     // thread-in-group (col within fragment)
    const int rowBase = blockIdx.y * 128;
    const int colBase = blockIdx.x * 128;
    const int m0w = (wid >> 2) * 64;   // warp row offset in CTA tile
    const int n0w = (wid & 3) * 32;    // warp col offset in CTA tile

    float acc[4][4][4];
#pragma unroll
    for (int mi = 0; mi < 4; mi++)
#pragma unroll
        for (int ni = 0; ni < 4; ni++)
#pragma unroll
            for (int r = 0; r < 4; r++) acc[mi][ni][r] = 0.f;

    const uint32_t* AHu = (const uint32_t*)AH;
    const uint32_t* ALu = (const uint32_t*)AL;
    const uint32_t* BHu = (const uint32_t*)BH;
    const uint32_t* BLu = (const uint32_t*)BL;

    for (int c = 0; c < 4; ++c) {
        // ---- fill A chunk: split into tf32 hi/lo (optional relu+bias) ----
        for (int i = tid; i < 2048; i += 256) {
            const int r  = i >> 4;
            const int c4 = (i & 15) * 4;
            const int gr = rowBase + r;
            float4 v = make_float4(0.f, 0.f, 0.f, 0.f);
            if (gr < NN)
                v = *(const float4*)(A + (size_t)gr * FD + c * KC + c4);
            if (RELU_BIAS) {
                const float4 bb = *(const float4*)(bias + c * KC + c4);
                v.x = fmaxf(v.x + bb.x, 0.f);
                v.y = fmaxf(v.y + bb.y, 0.f);
                v.z = fmaxf(v.z + bb.z, 0.f);
                v.w = fmaxf(v.w + bb.w, 0.f);
            }
            const float hx = tf32_rna(v.x), hy = tf32_rna(v.y);
            const float hz = tf32_rna(v.z), hw = tf32_rna(v.w);
            *(float4*)(AH + r * LDP + c4) = make_float4(hx, hy, hz, hw);
            *(float4*)(AL + r * LDP + c4) = make_float4(
                tf32_rna(v.x - hx), tf32_rna(v.y - hy),
                tf32_rna(v.z - hz), tf32_rna(v.w - hw));
        }
        // ---- fill B chunk (pre-split in global) ----
        for (int i = tid; i < 2048; i += 256) {
            const int n  = i >> 4;
            const int c4 = (i & 15) * 4;
            const int gn = colBase + n;
            *(float4*)(BH + n * LDP + c4) =
                *(const float4*)(BThi + (size_t)gn * FD + c * KC + c4);
            *(float4*)(BL + n * LDP + c4) =
                *(const float4*)(BTlo + (size_t)gn * FD + c * KC + c4);
        }
        __syncthreads();

        // ---- compute: 8 k-steps of m16n8k8 ----
#pragma unroll
        for (int ks = 0; ks < 8; ++ks) {
            const int kk = ks * 8;
            uint32_t ah[4][4], al[4][4], bh[4][2], bl[4][2];
#pragma unroll
            for (int mi = 0; mi < 4; mi++) {
                const int r0 = (m0w + mi * 16 + g) * LDP + kk + t;
                const int r1 = r0 + 8 * LDP;
                ah[mi][0] = AHu[r0];     ah[mi][1] = AHu[r1];
                ah[mi][2] = AHu[r0 + 4]; ah[mi][3] = AHu[r1 + 4];
                al[mi][0] = ALu[r0];     al[mi][1] = ALu[r1];
                al[mi][2] = ALu[r0 + 4]; al[mi][3] = ALu[r1 + 4];
            }
#pragma unroll
            for (int ni = 0; ni < 4; ni++) {
                const int b0 = (n0w + ni * 8 + g) * LDP + kk + t;
                bh[ni][0] = BHu[b0]; bh[ni][1] = BHu[b0 + 4];
                bl[ni][0] = BLu[b0]; bl[ni][1] = BLu[b0 + 4];
            }
#pragma unroll
            for (int mi = 0; mi < 4; mi++)
#pragma unroll
                for (int ni = 0; ni < 4; ni++) {
                    MMA_TF32(acc[mi][ni], ah[mi], bh[ni]);
                    MMA_TF32(acc[mi][ni], ah[mi], bl[ni]);
                    MMA_TF32(acc[mi][ni], al[mi], bh[ni]);
                }
        }
        __syncthreads();
    }

    // ---- epilogue: scattered float2 stores (full 32B sector coverage) ----
#pragma unroll
    for (int mi = 0; mi < 4; mi++) {
        const int r0 = rowBase + m0w + mi * 16 + g;
        const int r1 = r0 + 8;
#pragma unroll
        for (int ni = 0; ni < 4; ni++) {
            const int col = colBase + n0w + ni * 8 + 2 * t;
            if (r0 < NN)
                *(float2*)(C + (size_t)r0 * FD + col) =
                    make_float2(acc[mi][ni][0], acc[mi][ni][1]);
            if (r1 < NN)
                *(float2*)(C + (size_t)r1 * FD + col) =
                    make_float2(acc[mi][ni][2], acc[mi][ni][3]);
        }
    }
}

// ---------------------------------------------------------------------------
// Edge preprocessing: counting sort by destination node.
// ---------------------------------------------------------------------------
__global__ __launch_bounds__(256) void hist_kernel(const int* __restrict__ ei)
{
    const int e = blockIdx.x * 256 + threadIdx.x;
    if (e < NE) atomicAdd(&g_deg[ei[NE + e]], 1);
}

__global__ __launch_bounds__(1024) void scan_kernel()
{
    __shared__ int warpSums[32];
    const int lane = threadIdx.x & 31;
    const int wid  = threadIdx.x >> 5;
    int carry = 0;

    for (int base = 0; base < NN; base += 1024) {
        const int i = base + threadIdx.x;
        const int v = (i < NN) ? g_deg[i] : 0;
        int x = v;
#pragma unroll
        for (int o = 1; o < 32; o <<= 1) {
            int y = __shfl_up_sync(0xFFFFFFFFu, x, o);
            if (lane >= o) x += y;
        }
        if (lane == 31) warpSums[wid] = x;
        __syncthreads();
        if (threadIdx.x < 32) {
            int s = warpSums[threadIdx.x];
#pragma unroll
            for (int o = 1; o < 32; o <<= 1) {
                int y = __shfl_up_sync(0xFFFFFFFFu, s, o);
                if (threadIdx.x >= o) s += y;
            }
            warpSums[threadIdx.x] = s;
        }
        __syncthreads();
        const int warpPre = (wid > 0) ? warpSums[wid - 1] : 0;
        if (i < NN) g_off[i] = carry + warpPre + x - v;
        const int blockTotal = warpSums[31];
        __syncthreads();
        carry += blockTotal;
    }
    if (threadIdx.x == 0) g_off[NN] = carry;
}

__global__ __launch_bounds__(256) void sort_kernel(
    const int* __restrict__ ei, const float* __restrict__ w)
{
    const int e = blockIdx.x * 256 + threadIdx.x;
    if (e >= NE) return;
    const int dst = ei[NE + e];
    const int p = g_off[dst] + atomicAdd(&g_pos[dst], 1);
    g_srcS[p] = ei[e];
    g_wS[p]   = w[e];
}

// ---------------------------------------------------------------------------
// Segment aggregation: out[n] = sum_{e in seg(n)} w_e * h[src_e].
// ---------------------------------------------------------------------------
__global__ __launch_bounds__(256) void aggregate_kernel(
    const float* __restrict__ h, float* __restrict__ out)
{
    const int node = blockIdx.x * 4 + (threadIdx.x >> 6);
    if (node >= NN) return;
    const int j = (threadIdx.x & 63) * 4;

    const int eBeg = g_off[node];
    const int eEnd = g_off[node + 1];

    float4 acc = make_float4(0.f, 0.f, 0.f, 0.f);
    int e = eBeg;
    for (; e + 3 < eEnd; e += 4) {
        const int   s0 = g_srcS[e],     s1 = g_srcS[e + 1];
        const int   s2 = g_srcS[e + 2], s3 = g_srcS[e + 3];
        const float w0 = g_wS[e],       w1 = g_wS[e + 1];
        const float w2 = g_wS[e + 2],   w3 = g_wS[e + 3];
        const float4 v0 = *(const float4*)(h + (size_t)s0 * FD + j);
        const float4 v1 = *(const float4*)(h + (size_t)s1 * FD + j);
        const float4 v2 = *(const float4*)(h + (size_t)s2 * FD + j);
        const float4 v3 = *(const float4*)(h + (size_t)s3 * FD + j);
        acc.x = fmaf(w0, v0.x, acc.x); acc.y = fmaf(w0, v0.y, acc.y);
        acc.z = fmaf(w0, v0.z, acc.z); acc.w = fmaf(w0, v0.w, acc.w);
        acc.x = fmaf(w1, v1.x, acc.x); acc.y = fmaf(w1, v1.y, acc.y);
        acc.z = fmaf(w1, v1.z, acc.z); acc.w = fmaf(w1, v1.w, acc.w);
        acc.x = fmaf(w2, v2.x, acc.x); acc.y = fmaf(w2, v2.y, acc.y);
        acc.z = fmaf(w2, v2.z, acc.z); acc.w = fmaf(w2, v2.w, acc.w);
        acc.x = fmaf(w3, v3.x, acc.x); acc.y = fmaf(w3, v3.y, acc.y);
        acc.z = fmaf(w3, v3.z, acc.z); acc.w = fmaf(w3, v3.w, acc.w);
    }
    for (; e < eEnd; e++) {
        const int   s0 = g_srcS[e];
        const float w0 = g_wS[e];
        const float4 v0 = *(const float4*)(h + (size_t)s0 * FD + j);
        acc.x = fmaf(w0, v0.x, acc.x); acc.y = fmaf(w0, v0.y, acc.y);
        acc.z = fmaf(w0, v0.z, acc.z); acc.w = fmaf(w0, v0.w, acc.w);
    }
    *(float4*)(out + (size_t)node * FD + j) = acc;
}

// ---------------------------------------------------------------------------
// Query scorer (one warp per query) + log_softmax over 2 classes.
// ---------------------------------------------------------------------------
__global__ __launch_bounds__(256) void query_kernel(
    const float* __restrict__ agg2, const float* __restrict__ b2,
    const int* __restrict__ q, const float* __restrict__ Wl,
    const float* __restrict__ bl, float* __restrict__ out)
{
    __shared__ float sWl[512 * 2];
    __shared__ float sb2[FD];

    const int tid = threadIdx.x;
    for (int i = tid; i < 1024; i += 256) sWl[i] = Wl[i];
    if (tid < FD) sb2[tid] = b2[tid];
    __syncthreads();

    const int warp = tid >> 5;
    const int lane = tid & 31;
    const int qi = blockIdx.x * 8 + warp;
    if (qi >= NQ) return;

    const int n0 = q[qi * 2 + 0];
    const int n1 = q[qi * 2 + 1];

    float l0 = 0.f, l1 = 0.f;
#pragma unroll
    for (int tt = 0; tt < 8; tt++) {
        const int jj = tt * 32 + lane;
        const float v = agg2[(size_t)n0 * FD + jj] + sb2[jj];
        l0 = fmaf(v, sWl[jj * 2 + 0], l0);
        l1 = fmaf(v, sWl[jj * 2 + 1], l1);
    }
#pragma unroll
    for (int tt = 0; tt < 8; tt++) {
        const int jj = tt * 32 + lane;
        const float v = agg2[(size_t)n1 * FD + jj] + sb2[jj];
        l0 = fmaf(v, sWl[(256 + jj) * 2 + 0], l0);
        l1 = fmaf(v, sWl[(256 + jj) * 2 + 1], l1);
    }
#pragma unroll
    for (int o = 16; o; o >>= 1) {
        l0 += __shfl_down_sync(0xFFFFFFFFu, l0, o);
        l1 += __shfl_down_sync(0xFFFFFFFFu, l1, o);
    }
    if (lane == 0) {
        l0 += bl[0];
        l1 += bl[1];
        const float m = fmaxf(l0, l1);
        const float lse = m + logf(expf(l0 - m) + expf(l1 - m));
        out[qi * 2 + 0] = l0 - lse;
        out[qi * 2 + 1] = l1 - lse;
    }
}

extern "C" void kernel_launch(void* const* d_in, const int* in_sizes, int n_in,
                              void* d_out, int out_size)
{
    const float* x  = (const float*)d_in[0];
    const int*   ei = (const int*)  d_in[1];
    const int*   q  = (const int*)  d_in[2];
    const float* w  = (const float*)d_in[3];
    const float* W1 = (const float*)d_in[4];
    const float* b1 = (const float*)d_in[5];
    const float* W2 = (const float*)d_in[6];
    const float* b2 = (const float*)d_in[7];
    const float* Wl = (const float*)d_in[8];
    const float* bl = (const float*)d_in[9];
    float* out = (float*)d_out;

    float *bufA, *bufB, *b1hi, *b1lo, *b2hi, *b2lo;
    int *degP, *posP;
    cudaGetSymbolAddress((void**)&bufA, g_bufA);
    cudaGetSymbolAddress((void**)&bufB, g_bufB);
    cudaGetSymbolAddress((void**)&degP, g_deg);
    cudaGetSymbolAddress((void**)&posP, g_pos);
    cudaGetSymbolAddress((void**)&b1hi, g_B1hi);
    cudaGetSymbolAddress((void**)&b1lo, g_B1lo);
    cudaGetSymbolAddress((void**)&b2hi, g_B2hi);
    cudaGetSymbolAddress((void**)&b2lo, g_B2lo);

    cudaFuncSetAttribute(gemm_mma<false>,
                         cudaFuncAttributeMaxDynamicSharedMemorySize, GEMM_SMEM_BYTES);
    cudaFuncSetAttribute(gemm_mma<true>,
                         cudaFuncAttributeMaxDynamicSharedMemorySize, GEMM_SMEM_BYTES);

    const dim3 gemmGrid(2, (NN + 127) / 128);  // (2, 391)
    const int edgeBlocks = (NE + 255) / 256;
    const int aggBlocks  = (NN + 3) / 4;

    // ---- weight transpose + tf32 split ----
    wsplit_kernel<<<FD, FD>>>(W1, W2);

    // ---- edge preprocessing: counting sort by dst ----
    cudaMemsetAsync(degP, 0, NN * sizeof(int), 0);
    cudaMemsetAsync(posP, 0, NN * sizeof(int), 0);
    hist_kernel<<<edgeBlocks, 256>>>(ei);
    scan_kernel<<<1, 1024>>>();
    sort_kernel<<<edgeBlocks, 256>>>(ei, w);

    // ---- layer 1 ----
    gemm_mma<false><<<gemmGrid, 256, GEMM_SMEM_BYTES>>>(x, b1hi, b1lo, nullptr, bufA);
    aggregate_kernel<<<aggBlocks, 256>>>(bufA, bufB);

    // ---- layer 2 (relu + b1 fused into A-operand load) ----
    gemm_mma<true><<<gemmGrid, 256, GEMM_SMEM_BYTES>>>(bufB, b2hi, b2lo, b1, bufA);
    aggregate_kernel<<<aggBlocks, 256>>>(bufA, bufB);

    // ---- query scoring + log_softmax (b2 fused) ----
    query_kernel<<<(NQ + 7) / 8, 256>>>(bufB, b2, q, Wl, bl, out);
}